// round 9
// baseline (speedup 1.0000x reference)
#include <cuda_runtime.h>

#define D_IN   187
#define H_HID  50
#define C_OUT  5
#define LPR    4            // lanes per row
#define HP     13           // h per lane (52 padded)
#define TPB    128
#define RPB    (TPB/LPR)    // 32 rows per block
#define DCH    64           // d-chunk (3 chunks: 64+64+59)
#define SXP    65           // sx row pitch (odd -> conflict-free)
#define THR    1.0f
#define BETA   0.9f

// Shared layout (floats):
//  sW1: [dloc][j*20+i]  pitch 80/d; lane float4 bases {0,20,8,28}(+16*dl) -> conflict-free
//  sW2: [h][8] (h padded to 52); per-hh loop reads are 4-addr broadcast, conflict-free
//  sx : [r][SXP]
#define SM_W1   0
#define SM_W1_SZ (DCH * 80)              // 5120
#define SM_W2   (SM_W1 + SM_W1_SZ)
#define SM_W2_SZ (52 * 8)                // 416
#define SM_X    (SM_W2 + SM_W2_SZ)
#define SM_X_SZ (RPB * SXP)              // 2080
#define SMEM_BYTES ((SM_X + SM_X_SZ) * 4)   // 30464 B -> 6 blocks/SM fits 183KB

__global__ __launch_bounds__(TPB, 6)
void snn_fused_kernel(const float* __restrict__ x,
                      const float* __restrict__ W1,
                      const float* __restrict__ b1,
                      const float* __restrict__ W2,
                      const float* __restrict__ b2,
                      float* __restrict__ out,
                      int B, int steps)
{
    extern __shared__ float smem[];
    float* sW1 = smem + SM_W1;
    float* sW2 = smem + SM_W2;
    float* sx  = smem + SM_X;

    const int tid   = threadIdx.x;
    const int j     = tid & (LPR - 1);
    const int rloc  = tid >> 2;
    const int row   = blockIdx.x * RPB + rloc;
    const bool rowv = (row < B);
    const int hbase = j * HP;

    // ---- stage W2 [h][8], h>=50 zero ----
    for (int idx = tid; idx < 52 * C_OUT; idx += TPB) {
        int h = idx % 52, c = idx / 52;
        sW2[h * 8 + c] = (h < H_HID) ? W2[c * H_HID + h] : 0.0f;
    }

    // ---- phase 1: cur1 via exact ascending-k fma chain; W1/x staged in 3 d-chunks ----
    float cur1[HP];
#pragma unroll
    for (int i = 0; i < HP; ++i) cur1[i] = 0.0f;

    for (int d0 = 0; d0 < D_IN; d0 += DCH) {
        const int len = (D_IN - d0 < DCH) ? (D_IN - d0) : DCH;
        __syncthreads();
        // stage W1 chunk: gmem [h][d] -> sW1[dloc*80 + (h/13)*20 + h%13]
        for (int idx = tid; idx < 52 * len; idx += TPB) {
            int h = idx % 52, dloc = idx / 52;
            float v = (h < H_HID) ? W1[h * D_IN + d0 + dloc] : 0.0f;
            sW1[dloc * 80 + (h / HP) * 20 + (h % HP)] = v;
        }
        // stage x chunk
        for (int i2 = tid; i2 < RPB * len; i2 += TPB) {
            int r  = i2 / len;
            int dl = i2 - r * len;
            int gr = blockIdx.x * RPB + r;
            sx[r * SXP + dl] = (gr < B) ? x[(size_t)gr * D_IN + d0 + dl] : 0.0f;
        }
        __syncthreads();
        const float* xbase = &sx[rloc * SXP];
        const float* wbase = &sW1[j * 20];
        for (int dl = 0; dl < len; ++dl) {
            const float xv = xbase[dl];
            const float* wp = wbase + dl * 80;
            float4 wa = *(const float4*)(wp + 0);
            float4 wb = *(const float4*)(wp + 4);
            float4 wc = *(const float4*)(wp + 8);
            float  wd = wp[12];
            cur1[0]  = fmaf(wa.x, xv, cur1[0]);
            cur1[1]  = fmaf(wa.y, xv, cur1[1]);
            cur1[2]  = fmaf(wa.z, xv, cur1[2]);
            cur1[3]  = fmaf(wa.w, xv, cur1[3]);
            cur1[4]  = fmaf(wb.x, xv, cur1[4]);
            cur1[5]  = fmaf(wb.y, xv, cur1[5]);
            cur1[6]  = fmaf(wb.z, xv, cur1[6]);
            cur1[7]  = fmaf(wb.w, xv, cur1[7]);
            cur1[8]  = fmaf(wc.x, xv, cur1[8]);
            cur1[9]  = fmaf(wc.y, xv, cur1[9]);
            cur1[10] = fmaf(wc.z, xv, cur1[10]);
            cur1[11] = fmaf(wc.w, xv, cur1[11]);
            cur1[12] = fmaf(wd,   xv, cur1[12]);
        }
    }
    // bias: separate rounded add (reference epilogue); pad h -> 0
#pragma unroll
    for (int i = 0; i < HP; ++i) {
        int h = hbase + i;
        cur1[i] = (h < H_HID) ? __fadd_rn(cur1[i], b1[h]) : 0.0f;
    }

    // ---- phase 2: pair-relay. Lane j handles pair p = i - j (t = 2p, 2p+1).
    // Each t's 50-term cur2 chain stays exactly serial across lanes (shfl
    // relay). W2 read from shared per hh (broadcast, conflict-free) to keep
    // the register footprint at 6 blocks/SM. Pad h never spikes: exact no-ops.
    float mem1[HP];
#pragma unroll
    for (int i = 0; i < HP; ++i) mem1[i] = 0.0f;

    float P[2 * C_OUT];
#pragma unroll
    for (int c = 0; c < 2 * C_OUT; ++c) P[c] = 0.0f;

    float mem2[C_OUT], rb2[C_OUT];
#pragma unroll
    for (int c = 0; c < C_OUT; ++c) { mem2[c] = 0.0f; rb2[c] = b2[c]; }

    const size_t memoff = (size_t)steps * B * C_OUT;
    const int npairs = (steps + 1) >> 1;
    const int iters  = npairs + LPR - 1;
    const bool storer = (j == LPR - 1) && rowv;
    const float* w2base = &sW2[hbase * 8];

    for (int i = 0; i < iters; ++i) {
        float aA0 = __shfl_up_sync(0xFFFFFFFFu, P[0], 1, LPR);
        float aA1 = __shfl_up_sync(0xFFFFFFFFu, P[1], 1, LPR);
        float aA2 = __shfl_up_sync(0xFFFFFFFFu, P[2], 1, LPR);
        float aA3 = __shfl_up_sync(0xFFFFFFFFu, P[3], 1, LPR);
        float aA4 = __shfl_up_sync(0xFFFFFFFFu, P[4], 1, LPR);
        float aB0 = __shfl_up_sync(0xFFFFFFFFu, P[5], 1, LPR);
        float aB1 = __shfl_up_sync(0xFFFFFFFFu, P[6], 1, LPR);
        float aB2 = __shfl_up_sync(0xFFFFFFFFu, P[7], 1, LPR);
        float aB3 = __shfl_up_sync(0xFFFFFFFFu, P[8], 1, LPR);
        float aB4 = __shfl_up_sync(0xFFFFFFFFu, P[9], 1, LPR);

        const int p = i - j;
        if ((unsigned)p < (unsigned)npairs) {
            if (j == 0) {
                aA0 = 0.0f; aA1 = 0.0f; aA2 = 0.0f; aA3 = 0.0f; aA4 = 0.0f;
                aB0 = 0.0f; aB1 = 0.0f; aB2 = 0.0f; aB3 = 0.0f; aB4 = 0.0f;
            }

#pragma unroll
            for (int hh = 0; hh < HP; ++hh) {
                const float4 wv = *(const float4*)(w2base + hh * 8);
                const float  w4 = w2base[hh * 8 + 4];
                const float mo = mem1[hh];
                const float c1 = cur1[hh];
                const float r0 = (mo > THR) ? 1.0f : 0.0f;
                const float m1 = __fsub_rn(fmaf(BETA, mo, c1), r0);
                const float s1 = (m1 > THR) ? 1.0f : 0.0f;
                const float m2v = __fsub_rn(fmaf(BETA, m1, c1), s1);
                mem1[hh] = m2v;
                const float s2 = (m2v > THR) ? 1.0f : 0.0f;
                aA0 = fmaf(s1, wv.x, aA0);
                aA1 = fmaf(s1, wv.y, aA1);
                aA2 = fmaf(s1, wv.z, aA2);
                aA3 = fmaf(s1, wv.w, aA3);
                aA4 = fmaf(s1, w4,  aA4);
                aB0 = fmaf(s2, wv.x, aB0);
                aB1 = fmaf(s2, wv.y, aB1);
                aB2 = fmaf(s2, wv.z, aB2);
                aB3 = fmaf(s2, wv.w, aB3);
                aB4 = fmaf(s2, w4,  aB4);
            }
            P[0] = aA0; P[1] = aA1; P[2] = aA2; P[3] = aA3; P[4] = aA4;
            P[5] = aB0; P[6] = aB1; P[7] = aB2; P[8] = aB3; P[9] = aB4;

            if (storer) {
                const int t1 = 2 * p;
                const size_t ob1 = (size_t)t1 * B * C_OUT + (size_t)row * C_OUT;
#pragma unroll
                for (int c = 0; c < C_OUT; ++c) {
                    const float cur2 = __fadd_rn(P[c], rb2[c]);   // dot + b2
                    float m2 = mem2[c];
                    const float r2 = (m2 > THR) ? 1.0f : 0.0f;
                    m2 = __fsub_rn(fmaf(BETA, m2, cur2), r2);
                    mem2[c] = m2;
                    out[ob1 + c]          = (m2 > THR) ? 1.0f : 0.0f;
                    out[memoff + ob1 + c] = m2;
                }
                const int t2 = t1 + 1;
                if (t2 < steps) {
                    const size_t ob2 = ob1 + (size_t)B * C_OUT;
#pragma unroll
                    for (int c = 0; c < C_OUT; ++c) {
                        const float cur2 = __fadd_rn(P[5 + c], rb2[c]);
                        float m2 = mem2[c];
                        const float r2 = (m2 > THR) ? 1.0f : 0.0f;
                        m2 = __fsub_rn(fmaf(BETA, m2, cur2), r2);
                        mem2[c] = m2;
                        out[ob2 + c]          = (m2 > THR) ? 1.0f : 0.0f;
                        out[memoff + ob2 + c] = m2;
                    }
                }
            }
        }
    }
}

extern "C" void kernel_launch(void* const* d_in, const int* in_sizes, int n_in,
                              void* d_out, int out_size)
{
    const float* x  = (const float*)d_in[0];
    const float* W1 = (const float*)d_in[1];
    const float* b1 = (const float*)d_in[2];
    const float* W2 = (const float*)d_in[3];
    const float* b2 = (const float*)d_in[4];
    float* out = (float*)d_out;

    const int B = in_sizes[0] / D_IN;
    const int steps = (int)((long long)out_size / (2LL * B * C_OUT));

    cudaFuncSetAttribute(snn_fused_kernel,
                         cudaFuncAttributeMaxDynamicSharedMemorySize, SMEM_BYTES);

    const int grid = (B + RPB - 1) / RPB;
    snn_fused_kernel<<<grid, TPB, SMEM_BYTES>>>(x, W1, b1, W2, b2, out, B, steps);
}

// round 10
// speedup vs baseline: 1.0554x; 1.0554x over previous
#include <cuda_runtime.h>

#define D_IN   187
#define H_HID  50
#define C_OUT  5
#define LPR    4            // lanes per row
#define HP     13           // h per lane (52 padded)
#define TPB    128
#define RPB    (TPB/LPR)    // 32 rows per block
#define DCH    94           // d-chunk (2 chunks: 94 + 93)
#define SXP    100          // sx row pitch: 16B-aligned, bases mod 32 distinct
#define THR    1.0f
#define BETA   0.9f

// packed f32x2 helpers (two independent RN fp32 ops -> bit-identical to scalar)
#define FMA2(acc, s, w) asm("fma.rn.f32x2 %0, %1, %2, %0;" : "+l"(acc) : "l"(s), "l"(w))
#define DUP2(d, f)      asm("mov.b64 %0, {%1, %1};" : "=l"(d) : "f"(f))
#define UNPK2(lo, hi, d) asm("mov.b64 {%0, %1}, %2;" : "=f"(lo), "=f"(hi) : "l"(d))

// Shared layout (floats):
//  sW1: [dloc][j*20+i] pitch 80/d; lane float4/128b bases {0,20,8,28} mod 32 conflict-free
//  sW2: [h][8] (h padded to 52)
//  sx : [r][SXP]
#define SM_W1   0
#define SM_W1_SZ (DCH * 80)              // 7520
#define SM_W2   (SM_W1 + SM_W1_SZ)
#define SM_W2_SZ (52 * 8)                // 416
#define SM_X    (SM_W2 + SM_W2_SZ)
#define SM_X_SZ (RPB * SXP)              // 3200
#define SMEM_BYTES ((SM_X + SM_X_SZ) * 4)   // 44544 B -> 4 blocks/SM

__global__ __launch_bounds__(TPB, 4)
void snn_fused_kernel(const float* __restrict__ x,
                      const float* __restrict__ W1,
                      const float* __restrict__ b1,
                      const float* __restrict__ W2,
                      const float* __restrict__ b2,
                      float* __restrict__ out,
                      int B, int steps)
{
    extern __shared__ float smem[];
    float* sW1 = smem + SM_W1;
    float* sW2 = smem + SM_W2;
    float* sx  = smem + SM_X;

    const int tid   = threadIdx.x;
    const int j     = tid & (LPR - 1);
    const int rloc  = tid >> 2;
    const int row   = blockIdx.x * RPB + rloc;
    const bool rowv = (row < B);
    const int hbase = j * HP;

    // ---- stage W2 [h][8], h>=50 zero ----
    for (int idx = tid; idx < 52 * C_OUT; idx += TPB) {
        int h = idx % 52, c = idx / 52;
        sW2[h * 8 + c] = (h < H_HID) ? W2[c * H_HID + h] : 0.0f;
    }

    // ---- phase 1: cur1 via exact ascending-k fma chains, packed f32x2 ----
    unsigned long long A01 = 0ull, A23 = 0ull, A45 = 0ull,
                       A67 = 0ull, A89 = 0ull, Aab = 0ull;
    float a12 = 0.0f;

    for (int d0 = 0; d0 < D_IN; d0 += DCH) {
        const int len = (D_IN - d0 < DCH) ? (D_IN - d0) : DCH;
        __syncthreads();
        for (int idx = tid; idx < 52 * len; idx += TPB) {
            int h = idx % 52, dloc = idx / 52;
            float v = (h < H_HID) ? W1[h * D_IN + d0 + dloc] : 0.0f;
            sW1[dloc * 80 + (h / HP) * 20 + (h % HP)] = v;
        }
        for (int i2 = tid; i2 < RPB * len; i2 += TPB) {
            int r  = i2 / len;
            int dl = i2 - r * len;
            int gr = blockIdx.x * RPB + r;
            sx[r * SXP + dl] = (gr < B) ? x[(size_t)gr * D_IN + d0 + dl] : 0.0f;
        }
        __syncthreads();
        const float* xbase = &sx[rloc * SXP];
        const float* wbase = &sW1[j * 20];

#define GEMM_BODY(XV, DL) do {                                            \
            const float* wp = wbase + (DL) * 80;                          \
            unsigned long long xd; DUP2(xd, (XV));                        \
            ulonglong2 wA = *(const ulonglong2*)(wp);                     \
            ulonglong2 wB = *(const ulonglong2*)(wp + 4);                 \
            ulonglong2 wC = *(const ulonglong2*)(wp + 8);                 \
            float w12 = wp[12];                                           \
            FMA2(A01, xd, wA.x); FMA2(A23, xd, wA.y);                     \
            FMA2(A45, xd, wB.x); FMA2(A67, xd, wB.y);                     \
            FMA2(A89, xd, wC.x); FMA2(Aab, xd, wC.y);                     \
            a12 = fmaf(w12, (XV), a12);                                   \
        } while (0)

        const int q = len >> 2;
        const float4* xq = (const float4*)xbase;
        for (int g = 0; g < q; ++g) {
            float4 xv4 = xq[g];
            GEMM_BODY(xv4.x, 4 * g + 0);
            GEMM_BODY(xv4.y, 4 * g + 1);
            GEMM_BODY(xv4.z, 4 * g + 2);
            GEMM_BODY(xv4.w, 4 * g + 3);
        }
        for (int dl = q * 4; dl < len; ++dl) {
            GEMM_BODY(xbase[dl], dl);
        }
#undef GEMM_BODY
    }

    // unpack accumulators, bias as separate rounded add; pad h -> 0
    float cur1[HP];
    UNPK2(cur1[0],  cur1[1],  A01);
    UNPK2(cur1[2],  cur1[3],  A23);
    UNPK2(cur1[4],  cur1[5],  A45);
    UNPK2(cur1[6],  cur1[7],  A67);
    UNPK2(cur1[8],  cur1[9],  A89);
    UNPK2(cur1[10], cur1[11], Aab);
    cur1[12] = a12;
#pragma unroll
    for (int i = 0; i < HP; ++i) {
        int h = hbase + i;
        cur1[i] = (h < H_HID) ? __fadd_rn(cur1[i], b1[h]) : 0.0f;
    }

    // ---- W2 columns register-resident ----
    float w2r[HP][C_OUT];
#pragma unroll
    for (int i = 0; i < HP; ++i) {
        float4 a = *(const float4*)&sW2[(hbase + i) * 8];
        w2r[i][0] = a.x; w2r[i][1] = a.y; w2r[i][2] = a.z; w2r[i][3] = a.w;
        w2r[i][4] = sW2[(hbase + i) * 8 + 4];
    }

    // ---- phase 2: pair-relay (lane j handles pair p=i-j; t=2p,2p+1).
    // cur2's 50-term chain stays exactly serial across lanes via shfl relay.
    // Output stage: lane3's final P is broadcast to the 4-lane group; all
    // lanes redundantly (bit-identically) run the mem2 recurrence and each
    // stores one group {spkA,memA,spkB,memB} -> uniform single-STG-per-c.
    float mem1[HP];
#pragma unroll
    for (int i = 0; i < HP; ++i) mem1[i] = 0.0f;

    float P[2 * C_OUT];
#pragma unroll
    for (int c = 0; c < 2 * C_OUT; ++c) P[c] = 0.0f;

    float mem2[C_OUT], rb2[C_OUT];
#pragma unroll
    for (int c = 0; c < C_OUT; ++c) { mem2[c] = 0.0f; rb2[c] = b2[c]; }

    const size_t memoff = (size_t)steps * B * C_OUT;
    const size_t bstr   = (size_t)B * C_OUT;
    const int npairs = (steps + 1) >> 1;
    const int iters  = npairs + LPR - 1;
    // lane's store slot: j0=spkA, j1=memA, j2=spkB, j3=memB
    const size_t joff = ((j & 1) ? memoff : 0) + ((j & 2) ? bstr : 0);

    for (int i = 0; i < iters; ++i) {
        float aA0 = __shfl_up_sync(0xFFFFFFFFu, P[0], 1, LPR);
        float aA1 = __shfl_up_sync(0xFFFFFFFFu, P[1], 1, LPR);
        float aA2 = __shfl_up_sync(0xFFFFFFFFu, P[2], 1, LPR);
        float aA3 = __shfl_up_sync(0xFFFFFFFFu, P[3], 1, LPR);
        float aA4 = __shfl_up_sync(0xFFFFFFFFu, P[4], 1, LPR);
        float aB0 = __shfl_up_sync(0xFFFFFFFFu, P[5], 1, LPR);
        float aB1 = __shfl_up_sync(0xFFFFFFFFu, P[6], 1, LPR);
        float aB2 = __shfl_up_sync(0xFFFFFFFFu, P[7], 1, LPR);
        float aB3 = __shfl_up_sync(0xFFFFFFFFu, P[8], 1, LPR);
        float aB4 = __shfl_up_sync(0xFFFFFFFFu, P[9], 1, LPR);

        const int p = i - j;
        if ((unsigned)p < (unsigned)npairs) {
            if (j == 0) {
                aA0 = 0.0f; aA1 = 0.0f; aA2 = 0.0f; aA3 = 0.0f; aA4 = 0.0f;
                aB0 = 0.0f; aB1 = 0.0f; aB2 = 0.0f; aB3 = 0.0f; aB4 = 0.0f;
            }
#pragma unroll
            for (int hh = 0; hh < HP; ++hh) {
                const float mo = mem1[hh];
                const float c1 = cur1[hh];
                const float r0 = (mo > THR) ? 1.0f : 0.0f;
                const float m1 = __fsub_rn(fmaf(BETA, mo, c1), r0);
                const float s1 = (m1 > THR) ? 1.0f : 0.0f;
                const float m2v = __fsub_rn(fmaf(BETA, m1, c1), s1);
                mem1[hh] = m2v;
                const float s2 = (m2v > THR) ? 1.0f : 0.0f;
                aA0 = fmaf(s1, w2r[hh][0], aA0);
                aA1 = fmaf(s1, w2r[hh][1], aA1);
                aA2 = fmaf(s1, w2r[hh][2], aA2);
                aA3 = fmaf(s1, w2r[hh][3], aA3);
                aA4 = fmaf(s1, w2r[hh][4], aA4);
                aB0 = fmaf(s2, w2r[hh][0], aB0);
                aB1 = fmaf(s2, w2r[hh][1], aB1);
                aB2 = fmaf(s2, w2r[hh][2], aB2);
                aB3 = fmaf(s2, w2r[hh][3], aB3);
                aB4 = fmaf(s2, w2r[hh][4], aB4);
            }
            P[0] = aA0; P[1] = aA1; P[2] = aA2; P[3] = aA3; P[4] = aA4;
            P[5] = aB0; P[6] = aB1; P[7] = aB2; P[8] = aB3; P[9] = aB4;
        }

        // ---- output stage for lane3's pair p3 = i-3 (warp-uniform gate) ----
        const int p3 = i - (LPR - 1);
        if ((unsigned)p3 < (unsigned)npairs) {
            float F[2 * C_OUT];
#pragma unroll
            for (int c = 0; c < 2 * C_OUT; ++c)
                F[c] = __shfl_sync(0xFFFFFFFFu, P[c], LPR - 1, LPR);

            const int t1 = 2 * p3;
            const bool hasB = (t1 + 1 < steps);
            const size_t ob = (size_t)t1 * bstr + (size_t)row * C_OUT;
            float* outp = out + ob + joff;
            const bool dostore = rowv && ((j < 2) || hasB);

#pragma unroll
            for (int c = 0; c < C_OUT; ++c) {
                const float cur2A = __fadd_rn(F[c], rb2[c]);      // dot + b2
                float m2 = mem2[c];
                const float r2 = (m2 > THR) ? 1.0f : 0.0f;
                const float m2a = __fsub_rn(fmaf(BETA, m2, cur2A), r2);
                const float sA  = (m2a > THR) ? 1.0f : 0.0f;
                const float cur2B = __fadd_rn(F[C_OUT + c], rb2[c]);
                const float m2b = __fsub_rn(fmaf(BETA, m2a, cur2B), sA);
                const float sB  = (m2b > THR) ? 1.0f : 0.0f;
                mem2[c] = hasB ? m2b : m2a;
                // lane role select: j0=sA, j1=m2a, j2=sB, j3=m2b
                float val = (j & 1) ? m2a : sA;
                const float valB = (j & 1) ? m2b : sB;
                val = (j & 2) ? valB : val;
                if (dostore) outp[c] = val;
            }
        }
    }
}

extern "C" void kernel_launch(void* const* d_in, const int* in_sizes, int n_in,
                              void* d_out, int out_size)
{
    const float* x  = (const float*)d_in[0];
    const float* W1 = (const float*)d_in[1];
    const float* b1 = (const float*)d_in[2];
    const float* W2 = (const float*)d_in[3];
    const float* b2 = (const float*)d_in[4];
    float* out = (float*)d_out;

    const int B = in_sizes[0] / D_IN;
    const int steps = (int)((long long)out_size / (2LL * B * C_OUT));

    cudaFuncSetAttribute(snn_fused_kernel,
                         cudaFuncAttributeMaxDynamicSharedMemorySize, SMEM_BYTES);

    const int grid = (B + RPB - 1) / RPB;
    snn_fused_kernel<<<grid, TPB, SMEM_BYTES>>>(x, W1, b1, W2, b2, out, B, steps);
}

// round 11
// speedup vs baseline: 1.0926x; 1.0352x over previous
#include <cuda_runtime.h>

#define D_IN   187
#define H_HID  50
#define C_OUT  5
#define LPR    4            // lanes per row
#define HP     13           // h per lane (52 padded)
#define TPB    128
#define RPB    (TPB/LPR)    // 32 rows per block
#define DCH    94           // d-chunk (2 chunks: 94 + 93)
#define SXP    100          // sx row pitch: 16B-aligned, bases mod 32 distinct
#define THR    1.0f
#define BETA   0.9f

// packed f32x2 helpers (two independent RN fp32 ops -> bit-identical to scalar)
#define FMA2(acc, s, w) asm("fma.rn.f32x2 %0, %1, %2, %0;" : "+l"(acc) : "l"(s), "l"(w))
#define DUP2(d, f)      asm("mov.b64 %0, {%1, %1};" : "=l"(d) : "f"(f))
#define UNPK2(lo, hi, d) asm("mov.b64 {%0, %1}, %2;" : "=f"(lo), "=f"(hi) : "l"(d))

// Shared layout (floats):
//  sW1: [dloc][j*20+i] pitch 80/d; lane 128b bases {0,20,8,28} mod 32 conflict-free
//  sW2: [h][8] (h padded to 52)
//  sx : [r][SXP]
#define SM_W1   0
#define SM_W1_SZ (DCH * 80)              // 7520
#define SM_W2   (SM_W1 + SM_W1_SZ)
#define SM_W2_SZ (52 * 8)                // 416
#define SM_X    (SM_W2 + SM_W2_SZ)
#define SM_X_SZ (RPB * SXP)              // 3200
#define SMEM_BYTES ((SM_X + SM_X_SZ) * 4)   // 44544 B -> 4 blocks/SM

__global__ __launch_bounds__(TPB, 4)
void snn_fused_kernel(const float* __restrict__ x,
                      const float* __restrict__ W1,
                      const float* __restrict__ b1,
                      const float* __restrict__ W2,
                      const float* __restrict__ b2,
                      float* __restrict__ out,
                      int B, int steps)
{
    extern __shared__ float smem[];
    float* sW1 = smem + SM_W1;
    float* sW2 = smem + SM_W2;
    float* sx  = smem + SM_X;

    const int tid   = threadIdx.x;
    const int j     = tid & (LPR - 1);
    const int rloc  = tid >> 2;
    const int row   = blockIdx.x * RPB + rloc;
    const bool rowv = (row < B);
    const int hbase = j * HP;

    // ---- stage W2 [h][8], h>=50 zero ----
    for (int idx = tid; idx < 52 * C_OUT; idx += TPB) {
        int h = idx % 52, c = idx / 52;
        sW2[h * 8 + c] = (h < H_HID) ? W2[c * H_HID + h] : 0.0f;
    }

    // ---- phase 1: cur1 via exact ascending-k fma chains, packed f32x2 ----
    unsigned long long A01 = 0ull, A23 = 0ull, A45 = 0ull,
                       A67 = 0ull, A89 = 0ull, Aab = 0ull;
    float a12 = 0.0f;

    for (int d0 = 0; d0 < D_IN; d0 += DCH) {
        const int len = (D_IN - d0 < DCH) ? (D_IN - d0) : DCH;
        __syncthreads();
        for (int idx = tid; idx < 52 * len; idx += TPB) {
            int h = idx % 52, dloc = idx / 52;
            float v = (h < H_HID) ? W1[h * D_IN + d0 + dloc] : 0.0f;
            sW1[dloc * 80 + (h / HP) * 20 + (h % HP)] = v;
        }
        for (int i2 = tid; i2 < RPB * len; i2 += TPB) {
            int r  = i2 / len;
            int dl = i2 - r * len;
            int gr = blockIdx.x * RPB + r;
            sx[r * SXP + dl] = (gr < B) ? x[(size_t)gr * D_IN + d0 + dl] : 0.0f;
        }
        __syncthreads();
        const float* xbase = &sx[rloc * SXP];
        const float* wbase = &sW1[j * 20];

#define GEMM_BODY(XV, DL) do {                                            \
            const float* wp = wbase + (DL) * 80;                          \
            unsigned long long xd; DUP2(xd, (XV));                        \
            ulonglong2 wA = *(const ulonglong2*)(wp);                     \
            ulonglong2 wB = *(const ulonglong2*)(wp + 4);                 \
            ulonglong2 wC = *(const ulonglong2*)(wp + 8);                 \
            float w12 = wp[12];                                           \
            FMA2(A01, xd, wA.x); FMA2(A23, xd, wA.y);                     \
            FMA2(A45, xd, wB.x); FMA2(A67, xd, wB.y);                     \
            FMA2(A89, xd, wC.x); FMA2(Aab, xd, wC.y);                     \
            a12 = fmaf(w12, (XV), a12);                                   \
        } while (0)

        const int q = len >> 2;
        const float4* xq = (const float4*)xbase;
        for (int g = 0; g < q; ++g) {
            float4 xv4 = xq[g];
            GEMM_BODY(xv4.x, 4 * g + 0);
            GEMM_BODY(xv4.y, 4 * g + 1);
            GEMM_BODY(xv4.z, 4 * g + 2);
            GEMM_BODY(xv4.w, 4 * g + 3);
        }
        for (int dl = q * 4; dl < len; ++dl) {
            GEMM_BODY(xbase[dl], dl);
        }
#undef GEMM_BODY
    }

    // unpack accumulators, bias as separate rounded add; pad h -> 0
    float cur1[HP];
    UNPK2(cur1[0],  cur1[1],  A01);
    UNPK2(cur1[2],  cur1[3],  A23);
    UNPK2(cur1[4],  cur1[5],  A45);
    UNPK2(cur1[6],  cur1[7],  A67);
    UNPK2(cur1[8],  cur1[9],  A89);
    UNPK2(cur1[10], cur1[11], Aab);
    cur1[12] = a12;
#pragma unroll
    for (int i = 0; i < HP; ++i) {
        int h = hbase + i;
        cur1[i] = (h < H_HID) ? __fadd_rn(cur1[i], b1[h]) : 0.0f;
    }

    // ---- W2 columns register-resident ----
    float w2r[HP][C_OUT];
#pragma unroll
    for (int i = 0; i < HP; ++i) {
        float4 a = *(const float4*)&sW2[(hbase + i) * 8];
        w2r[i][0] = a.x; w2r[i][1] = a.y; w2r[i][2] = a.z; w2r[i][3] = a.w;
        w2r[i][4] = sW2[(hbase + i) * 8 + 4];
    }

    // ---- phase 2: pair-relay (lane j handles pair p = i - j; t = 2p, 2p+1).
    // Each t's 50-term cur2 chain stays exactly serial across lanes (shfl
    // relay); two timesteps per pair give 2x ILP on the serial chains.
    // Pad h never spikes (cur1=0, w2=0): exact no-ops. Store stage: R8's
    // proven divergent lane-3 form.
    float mem1[HP];
#pragma unroll
    for (int i = 0; i < HP; ++i) mem1[i] = 0.0f;

    float P[2 * C_OUT];
#pragma unroll
    for (int c = 0; c < 2 * C_OUT; ++c) P[c] = 0.0f;

    float mem2[C_OUT], rb2[C_OUT];
#pragma unroll
    for (int c = 0; c < C_OUT; ++c) { mem2[c] = 0.0f; rb2[c] = b2[c]; }

    const size_t memoff = (size_t)steps * B * C_OUT;
    const int npairs = (steps + 1) >> 1;
    const int iters  = npairs + LPR - 1;
    const bool storer = (j == LPR - 1) && rowv;

    for (int i = 0; i < iters; ++i) {
        float q[2 * C_OUT];
#pragma unroll
        for (int c = 0; c < 2 * C_OUT; ++c)
            q[c] = __shfl_up_sync(0xFFFFFFFFu, P[c], 1, LPR);

        const int p = i - j;
        if ((unsigned)p < (unsigned)npairs) {
            float aA0 = (j == 0) ? 0.0f : q[0];
            float aA1 = (j == 0) ? 0.0f : q[1];
            float aA2 = (j == 0) ? 0.0f : q[2];
            float aA3 = (j == 0) ? 0.0f : q[3];
            float aA4 = (j == 0) ? 0.0f : q[4];
            float aB0 = (j == 0) ? 0.0f : q[5];
            float aB1 = (j == 0) ? 0.0f : q[6];
            float aB2 = (j == 0) ? 0.0f : q[7];
            float aB3 = (j == 0) ? 0.0f : q[8];
            float aB4 = (j == 0) ? 0.0f : q[9];

#pragma unroll
            for (int hh = 0; hh < HP; ++hh) {
                const float mo = mem1[hh];
                const float c1 = cur1[hh];
                const float r0 = (mo > THR) ? 1.0f : 0.0f;
                const float m1 = __fsub_rn(fmaf(BETA, mo, c1), r0);
                const float s1 = (m1 > THR) ? 1.0f : 0.0f;
                const float m2v = __fsub_rn(fmaf(BETA, m1, c1), s1);
                mem1[hh] = m2v;
                const float s2 = (m2v > THR) ? 1.0f : 0.0f;
                aA0 = fmaf(s1, w2r[hh][0], aA0);
                aA1 = fmaf(s1, w2r[hh][1], aA1);
                aA2 = fmaf(s1, w2r[hh][2], aA2);
                aA3 = fmaf(s1, w2r[hh][3], aA3);
                aA4 = fmaf(s1, w2r[hh][4], aA4);
                aB0 = fmaf(s2, w2r[hh][0], aB0);
                aB1 = fmaf(s2, w2r[hh][1], aB1);
                aB2 = fmaf(s2, w2r[hh][2], aB2);
                aB3 = fmaf(s2, w2r[hh][3], aB3);
                aB4 = fmaf(s2, w2r[hh][4], aB4);
            }
            P[0] = aA0; P[1] = aA1; P[2] = aA2; P[3] = aA3; P[4] = aA4;
            P[5] = aB0; P[6] = aB1; P[7] = aB2; P[8] = aB3; P[9] = aB4;

            if (storer) {
                const int t1 = 2 * p;
                const size_t ob1 = (size_t)t1 * B * C_OUT + (size_t)row * C_OUT;
#pragma unroll
                for (int c = 0; c < C_OUT; ++c) {
                    const float cur2 = __fadd_rn(P[c], rb2[c]);   // dot + b2
                    float m2 = mem2[c];
                    const float r2 = (m2 > THR) ? 1.0f : 0.0f;
                    m2 = __fsub_rn(fmaf(BETA, m2, cur2), r2);
                    mem2[c] = m2;
                    out[ob1 + c]          = (m2 > THR) ? 1.0f : 0.0f;
                    out[memoff + ob1 + c] = m2;
                }
                const int t2 = t1 + 1;
                if (t2 < steps) {
                    const size_t ob2 = ob1 + (size_t)B * C_OUT;
#pragma unroll
                    for (int c = 0; c < C_OUT; ++c) {
                        const float cur2 = __fadd_rn(P[5 + c], rb2[c]);
                        float m2 = mem2[c];
                        const float r2 = (m2 > THR) ? 1.0f : 0.0f;
                        m2 = __fsub_rn(fmaf(BETA, m2, cur2), r2);
                        mem2[c] = m2;
                        out[ob2 + c]          = (m2 > THR) ? 1.0f : 0.0f;
                        out[memoff + ob2 + c] = m2;
                    }
                }
            }
        }
    }
}

extern "C" void kernel_launch(void* const* d_in, const int* in_sizes, int n_in,
                              void* d_out, int out_size)
{
    const float* x  = (const float*)d_in[0];
    const float* W1 = (const float*)d_in[1];
    const float* b1 = (const float*)d_in[2];
    const float* W2 = (const float*)d_in[3];
    const float* b2 = (const float*)d_in[4];
    float* out = (float*)d_out;

    const int B = in_sizes[0] / D_IN;
    const int steps = (int)((long long)out_size / (2LL * B * C_OUT));

    cudaFuncSetAttribute(snn_fused_kernel,
                         cudaFuncAttributeMaxDynamicSharedMemorySize, SMEM_BYTES);

    const int grid = (B + RPB - 1) / RPB;
    snn_fused_kernel<<<grid, TPB, SMEM_BYTES>>>(x, W1, b1, W2, b2, out, B, steps);
}

// round 12
// speedup vs baseline: 1.0981x; 1.0051x over previous
#include <cuda_runtime.h>

#define D_IN   187
#define H_HID  50
#define C_OUT  5
#define LPR    4            // lanes per row
#define HP     13           // h per lane (52 padded)
#define TPB    128
#define RPB    (TPB/LPR)    // 32 rows per block
#define DCH    94           // d-chunk (2 chunks: 94 + 93)
#define SXP    100          // sx row pitch: 16B-aligned, bases mod 32 distinct
#define THR    1.0f
#define BETA   0.9f

typedef unsigned long long u64;

// packed f32x2 helpers (two independent RN fp32 ops -> bit-identical to scalar)
#define FMA2(acc, s, w) asm("fma.rn.f32x2 %0, %1, %2, %0;" : "+l"(acc) : "l"(s), "l"(w))
#define DUP2(d, f)      asm("mov.b64 %0, {%1, %1};" : "=l"(d) : "f"(f))
#define UNPK2(lo, hi, d) asm("mov.b64 {%0, %1}, %2;" : "=f"(lo), "=f"(hi) : "l"(d))

// Shared layout (floats):
//  sW1: [dloc][j*20+i] pitch 80/d; lane 128b bases {0,20,8,28} mod 32 conflict-free
//  sW2: [h][8] (h padded to 52)
//  sx : [r][SXP]
#define SM_W1   0
#define SM_W1_SZ (DCH * 80)              // 7520
#define SM_W2   (SM_W1 + SM_W1_SZ)
#define SM_W2_SZ (52 * 8)                // 416
#define SM_X    (SM_W2 + SM_W2_SZ)
#define SM_X_SZ (RPB * SXP)              // 3200
#define SMEM_BYTES ((SM_X + SM_X_SZ) * 4)   // 44544 B -> 4 blocks/SM

__global__ __launch_bounds__(TPB, 4)
void snn_fused_kernel(const float* __restrict__ x,
                      const float* __restrict__ W1,
                      const float* __restrict__ b1,
                      const float* __restrict__ W2,
                      const float* __restrict__ b2,
                      float* __restrict__ out,
                      int B, int steps)
{
    extern __shared__ float smem[];
    float* sW1 = smem + SM_W1;
    float* sW2 = smem + SM_W2;
    float* sx  = smem + SM_X;

    const int tid   = threadIdx.x;
    const int j     = tid & (LPR - 1);
    const int rloc  = tid >> 2;
    const int row   = blockIdx.x * RPB + rloc;
    const bool rowv = (row < B);
    const int hbase = j * HP;

    // ---- stage W2 [h][8], h>=50 zero ----
    for (int idx = tid; idx < 52 * C_OUT; idx += TPB) {
        int h = idx % 52, c = idx / 52;
        sW2[h * 8 + c] = (h < H_HID) ? W2[c * H_HID + h] : 0.0f;
    }

    // ---- phase 1: cur1 via exact ascending-k fma chains, packed f32x2 ----
    u64 A01 = 0ull, A23 = 0ull, A45 = 0ull, A67 = 0ull, A89 = 0ull, Aab = 0ull;
    float a12 = 0.0f;

    for (int d0 = 0; d0 < D_IN; d0 += DCH) {
        const int len = (D_IN - d0 < DCH) ? (D_IN - d0) : DCH;
        __syncthreads();
        for (int idx = tid; idx < 52 * len; idx += TPB) {
            int h = idx % 52, dloc = idx / 52;
            float v = (h < H_HID) ? W1[h * D_IN + d0 + dloc] : 0.0f;
            sW1[dloc * 80 + (h / HP) * 20 + (h % HP)] = v;
        }
        for (int i2 = tid; i2 < RPB * len; i2 += TPB) {
            int r  = i2 / len;
            int dl = i2 - r * len;
            int gr = blockIdx.x * RPB + r;
            sx[r * SXP + dl] = (gr < B) ? x[(size_t)gr * D_IN + d0 + dl] : 0.0f;
        }
        __syncthreads();
        const float* xbase = &sx[rloc * SXP];
        const float* wbase = &sW1[j * 20];

#define GEMM_BODY(XV, DL) do {                                            \
            const float* wp = wbase + (DL) * 80;                          \
            u64 xd; DUP2(xd, (XV));                                       \
            ulonglong2 wA = *(const ulonglong2*)(wp);                     \
            ulonglong2 wB = *(const ulonglong2*)(wp + 4);                 \
            ulonglong2 wC = *(const ulonglong2*)(wp + 8);                 \
            float w12 = wp[12];                                           \
            FMA2(A01, xd, wA.x); FMA2(A23, xd, wA.y);                     \
            FMA2(A45, xd, wB.x); FMA2(A67, xd, wB.y);                     \
            FMA2(A89, xd, wC.x); FMA2(Aab, xd, wC.y);                     \
            a12 = fmaf(w12, (XV), a12);                                   \
        } while (0)

        const int q4 = len >> 2;
        const float4* xq = (const float4*)xbase;
        for (int g = 0; g < q4; ++g) {
            float4 xv4 = xq[g];
            GEMM_BODY(xv4.x, 4 * g + 0);
            GEMM_BODY(xv4.y, 4 * g + 1);
            GEMM_BODY(xv4.z, 4 * g + 2);
            GEMM_BODY(xv4.w, 4 * g + 3);
        }
        for (int dl = q4 * 4; dl < len; ++dl) {
            GEMM_BODY(xbase[dl], dl);
        }
#undef GEMM_BODY
    }

    // unpack accumulators, bias as separate rounded add; pad h -> 0
    float cur1[HP];
    UNPK2(cur1[0],  cur1[1],  A01);
    UNPK2(cur1[2],  cur1[3],  A23);
    UNPK2(cur1[4],  cur1[5],  A45);
    UNPK2(cur1[6],  cur1[7],  A67);
    UNPK2(cur1[8],  cur1[9],  A89);
    UNPK2(cur1[10], cur1[11], Aab);
    cur1[12] = a12;
#pragma unroll
    for (int i = 0; i < HP; ++i) {
        int h = hbase + i;
        cur1[i] = (h < H_HID) ? __fadd_rn(cur1[i], b1[h]) : 0.0f;
    }

    // ---- W2 pairs register-resident, PRE-PACKED as f32x2 ----
    // w01[hh] = (w2[h][0], w2[h][1]), w23[hh] = (w2[h][2], w2[h][3]), w4 scalar
    u64 w01[HP], w23[HP];
    float w4[HP];
#pragma unroll
    for (int i = 0; i < HP; ++i) {
        const float* wr = &sW2[(hbase + i) * 8];
        w01[i] = *(const u64*)(wr + 0);
        w23[i] = *(const u64*)(wr + 2);
        w4[i]  = wr[4];
    }

    // ---- phase 2: pair-relay (lane j handles pair p = i - j; t = 2p, 2p+1).
    // Accumulator chains packed as f32x2: lanes of each packed chain are the
    // exact scalar chains of R8 (independent RN fp32) -> bit-identical.
    // Partials relayed packed (u64 shfl). Store stage: R8's divergent lane-3.
    float mem1[HP];
#pragma unroll
    for (int i = 0; i < HP; ++i) mem1[i] = 0.0f;

    u64 PA01 = 0ull, PA23 = 0ull, PB01 = 0ull, PB23 = 0ull;
    float PA4 = 0.0f, PB4 = 0.0f;

    float mem2[C_OUT], rb2[C_OUT];
#pragma unroll
    for (int c = 0; c < C_OUT; ++c) { mem2[c] = 0.0f; rb2[c] = b2[c]; }

    const size_t memoff = (size_t)steps * B * C_OUT;
    const int npairs = (steps + 1) >> 1;
    const int iters  = npairs + LPR - 1;
    const bool storer = (j == LPR - 1) && rowv;

    for (int i = 0; i < iters; ++i) {
        u64 qA01 = __shfl_up_sync(0xFFFFFFFFu, PA01, 1, LPR);
        u64 qA23 = __shfl_up_sync(0xFFFFFFFFu, PA23, 1, LPR);
        u64 qB01 = __shfl_up_sync(0xFFFFFFFFu, PB01, 1, LPR);
        u64 qB23 = __shfl_up_sync(0xFFFFFFFFu, PB23, 1, LPR);
        float qA4 = __shfl_up_sync(0xFFFFFFFFu, PA4, 1, LPR);
        float qB4 = __shfl_up_sync(0xFFFFFFFFu, PB4, 1, LPR);

        const int p = i - j;
        if ((unsigned)p < (unsigned)npairs) {
            u64 aA01 = (j == 0) ? 0ull : qA01;
            u64 aA23 = (j == 0) ? 0ull : qA23;
            u64 aB01 = (j == 0) ? 0ull : qB01;
            u64 aB23 = (j == 0) ? 0ull : qB23;
            float aA4 = (j == 0) ? 0.0f : qA4;
            float aB4 = (j == 0) ? 0.0f : qB4;

#pragma unroll
            for (int hh = 0; hh < HP; ++hh) {
                const float mo = mem1[hh];
                const float c1 = cur1[hh];
                const float r0 = (mo > THR) ? 1.0f : 0.0f;
                const float m1 = __fsub_rn(fmaf(BETA, mo, c1), r0);
                const float s1 = (m1 > THR) ? 1.0f : 0.0f;
                const float m2v = __fsub_rn(fmaf(BETA, m1, c1), s1);
                mem1[hh] = m2v;
                const float s2 = (m2v > THR) ? 1.0f : 0.0f;
                u64 s1d; DUP2(s1d, s1);
                u64 s2d; DUP2(s2d, s2);
                FMA2(aA01, s1d, w01[hh]);
                FMA2(aA23, s1d, w23[hh]);
                aA4 = fmaf(s1, w4[hh], aA4);
                FMA2(aB01, s2d, w01[hh]);
                FMA2(aB23, s2d, w23[hh]);
                aB4 = fmaf(s2, w4[hh], aB4);
            }
            PA01 = aA01; PA23 = aA23; PA4 = aA4;
            PB01 = aB01; PB23 = aB23; PB4 = aB4;

            if (storer) {
                float PF[2 * C_OUT];
                UNPK2(PF[0], PF[1], PA01);
                UNPK2(PF[2], PF[3], PA23);
                PF[4] = PA4;
                UNPK2(PF[5], PF[6], PB01);
                UNPK2(PF[7], PF[8], PB23);
                PF[9] = PB4;

                const int t1 = 2 * p;
                const size_t ob1 = (size_t)t1 * B * C_OUT + (size_t)row * C_OUT;
#pragma unroll
                for (int c = 0; c < C_OUT; ++c) {
                    const float cur2 = __fadd_rn(PF[c], rb2[c]);   // dot + b2
                    float m2 = mem2[c];
                    const float r2 = (m2 > THR) ? 1.0f : 0.0f;
                    m2 = __fsub_rn(fmaf(BETA, m2, cur2), r2);
                    mem2[c] = m2;
                    out[ob1 + c]          = (m2 > THR) ? 1.0f : 0.0f;
                    out[memoff + ob1 + c] = m2;
                }
                const int t2 = t1 + 1;
                if (t2 < steps) {
                    const size_t ob2 = ob1 + (size_t)B * C_OUT;
#pragma unroll
                    for (int c = 0; c < C_OUT; ++c) {
                        const float cur2 = __fadd_rn(PF[5 + c], rb2[c]);
                        float m2 = mem2[c];
                        const float r2 = (m2 > THR) ? 1.0f : 0.0f;
                        m2 = __fsub_rn(fmaf(BETA, m2, cur2), r2);
                        mem2[c] = m2;
                        out[ob2 + c]          = (m2 > THR) ? 1.0f : 0.0f;
                        out[memoff + ob2 + c] = m2;
                    }
                }
            }
        }
    }
}

extern "C" void kernel_launch(void* const* d_in, const int* in_sizes, int n_in,
                              void* d_out, int out_size)
{
    const float* x  = (const float*)d_in[0];
    const float* W1 = (const float*)d_in[1];
    const float* b1 = (const float*)d_in[2];
    const float* W2 = (const float*)d_in[3];
    const float* b2 = (const float*)d_in[4];
    float* out = (float*)d_out;

    const int B = in_sizes[0] / D_IN;
    const int steps = (int)((long long)out_size / (2LL * B * C_OUT));

    cudaFuncSetAttribute(snn_fused_kernel,
                         cudaFuncAttributeMaxDynamicSharedMemorySize, SMEM_BYTES);

    const int grid = (B + RPB - 1) / RPB;
    snn_fused_kernel<<<grid, TPB, SMEM_BYTES>>>(x, W1, b1, W2, b2, out, B, steps);
}

// round 13
// speedup vs baseline: 1.0983x; 1.0002x over previous
#include <cuda_runtime.h>

#define D_IN   187
#define H_HID  50
#define C_OUT  5
#define LPR    4            // lanes per row
#define HP     13           // h per lane (52 padded)
#define TPB    128
#define RPB    (TPB/LPR)    // 32 rows per block
#define TQ     4            // timesteps per relay hop
#define DCH    64           // d-chunk (3 chunks: 64+64+59)
#define SXP    68           // sx row pitch: 16B-aligned, bases mod 32 distinct
#define THR    1.0f
#define BETA   0.9f

typedef unsigned long long u64;

// packed f32x2 helpers (two independent RN fp32 ops -> bit-identical to scalar)
#define FMA2(acc, s, w) asm("fma.rn.f32x2 %0, %1, %2, %0;" : "+l"(acc) : "l"(s), "l"(w))
#define DUP2(d, f)      asm("mov.b64 %0, {%1, %1};" : "=l"(d) : "f"(f))
#define UNPK2(lo, hi, d) asm("mov.b64 {%0, %1}, %2;" : "=f"(lo), "=f"(hi) : "l"(d))

// Shared layout (floats):
//  sW1: [dloc][j*20+i] pitch 80/d; lane 128b bases {0,20,8,28} mod 32 conflict-free
//  sW2: [h][8] (h padded to 52); per-hh 16B loads at h*32B -> conflict-free
//  sx : [r][SXP]
#define SM_W1   0
#define SM_W1_SZ (DCH * 80)              // 5120
#define SM_W2   (SM_W1 + SM_W1_SZ)
#define SM_W2_SZ (52 * 8)                // 416
#define SM_X    (SM_W2 + SM_W2_SZ)
#define SM_X_SZ (RPB * SXP)              // 2176
#define SMEM_BYTES ((SM_X + SM_X_SZ) * 4)   // 30848 B -> 6 blocks/SM

__global__ __launch_bounds__(TPB, 6)
void snn_fused_kernel(const float* __restrict__ x,
                      const float* __restrict__ W1,
                      const float* __restrict__ b1,
                      const float* __restrict__ W2,
                      const float* __restrict__ b2,
                      float* __restrict__ out,
                      int B, int steps)
{
    extern __shared__ float smem[];
    float* sW1 = smem + SM_W1;
    float* sW2 = smem + SM_W2;
    float* sx  = smem + SM_X;

    const int tid   = threadIdx.x;
    const int j     = tid & (LPR - 1);
    const int rloc  = tid >> 2;
    const int row   = blockIdx.x * RPB + rloc;
    const bool rowv = (row < B);
    const int hbase = j * HP;

    // ---- stage W2 [h][8], h>=50 zero ----
    for (int idx = tid; idx < 52 * C_OUT; idx += TPB) {
        int h = idx % 52, c = idx / 52;
        sW2[h * 8 + c] = (h < H_HID) ? W2[c * H_HID + h] : 0.0f;
    }

    // ---- phase 1: cur1 via exact ascending-k fma chains, packed f32x2 ----
    u64 A01 = 0ull, A23 = 0ull, A45 = 0ull, A67 = 0ull, A89 = 0ull, Aab = 0ull;
    float a12 = 0.0f;

    for (int d0 = 0; d0 < D_IN; d0 += DCH) {
        const int len = (D_IN - d0 < DCH) ? (D_IN - d0) : DCH;
        __syncthreads();
        for (int idx = tid; idx < 52 * len; idx += TPB) {
            int h = idx % 52, dloc = idx / 52;
            float v = (h < H_HID) ? W1[h * D_IN + d0 + dloc] : 0.0f;
            sW1[dloc * 80 + (h / HP) * 20 + (h % HP)] = v;
        }
        for (int i2 = tid; i2 < RPB * len; i2 += TPB) {
            int r  = i2 / len;
            int dl = i2 - r * len;
            int gr = blockIdx.x * RPB + r;
            sx[r * SXP + dl] = (gr < B) ? x[(size_t)gr * D_IN + d0 + dl] : 0.0f;
        }
        __syncthreads();
        const float* xbase = &sx[rloc * SXP];
        const float* wbase = &sW1[j * 20];

#define GEMM_BODY(XV, DL) do {                                            \
            const float* wp = wbase + (DL) * 80;                          \
            u64 xd; DUP2(xd, (XV));                                       \
            ulonglong2 wA = *(const ulonglong2*)(wp);                     \
            ulonglong2 wB = *(const ulonglong2*)(wp + 4);                 \
            ulonglong2 wC = *(const ulonglong2*)(wp + 8);                 \
            float w12 = wp[12];                                           \
            FMA2(A01, xd, wA.x); FMA2(A23, xd, wA.y);                     \
            FMA2(A45, xd, wB.x); FMA2(A67, xd, wB.y);                     \
            FMA2(A89, xd, wC.x); FMA2(Aab, xd, wC.y);                     \
            a12 = fmaf(w12, (XV), a12);                                   \
        } while (0)

        const int q4 = len >> 2;
        const float4* xq = (const float4*)xbase;
        for (int g = 0; g < q4; ++g) {
            float4 xv4 = xq[g];
            GEMM_BODY(xv4.x, 4 * g + 0);
            GEMM_BODY(xv4.y, 4 * g + 1);
            GEMM_BODY(xv4.z, 4 * g + 2);
            GEMM_BODY(xv4.w, 4 * g + 3);
        }
        for (int dl = q4 * 4; dl < len; ++dl) {
            GEMM_BODY(xbase[dl], dl);
        }
#undef GEMM_BODY
    }

    // unpack accumulators, bias as separate rounded add; pad h -> 0
    float cur1[HP];
    UNPK2(cur1[0],  cur1[1],  A01);
    UNPK2(cur1[2],  cur1[3],  A23);
    UNPK2(cur1[4],  cur1[5],  A45);
    UNPK2(cur1[6],  cur1[7],  A67);
    UNPK2(cur1[8],  cur1[9],  A89);
    UNPK2(cur1[10], cur1[11], Aab);
    cur1[12] = a12;
#pragma unroll
    for (int i = 0; i < HP; ++i) {
        int h = hbase + i;
        cur1[i] = (h < H_HID) ? __fadd_rn(cur1[i], b1[h]) : 0.0f;
    }

    // ---- phase 2: quad-relay. Lane j handles quad p = i - j (t = 4p..4p+3).
    // Each t's 50-term cur2 chain stays exactly serial across lanes (shfl
    // relay); 4 timesteps per hop -> 12 independent packed accumulate chains
    // (great ILP) and W2 LDS amortized over 12 FMAs. Pad h never spikes
    // (cur1=0, w2=0): exact no-ops.
    float mem1[HP];
#pragma unroll
    for (int i = 0; i < HP; ++i) mem1[i] = 0.0f;

    u64 P01[TQ], P23[TQ];      // packed partial c2 (cols 0-1, 2-3) per step
    float P4[TQ];              // col 4
#pragma unroll
    for (int k = 0; k < TQ; ++k) { P01[k] = 0ull; P23[k] = 0ull; P4[k] = 0.0f; }

    float mem2[C_OUT], rb2[C_OUT];
#pragma unroll
    for (int c = 0; c < C_OUT; ++c) { mem2[c] = 0.0f; rb2[c] = b2[c]; }

    const size_t memoff = (size_t)steps * B * C_OUT;
    const size_t bstr   = (size_t)B * C_OUT;
    const int nquads = (steps + TQ - 1) / TQ;
    const int iters  = nquads + LPR - 1;
    const bool storer = (j == LPR - 1) && rowv;
    const float* w2p = &sW2[hbase * 8];

    for (int i = 0; i < iters; ++i) {
        u64 q01[TQ], q23[TQ];
        float q4v[TQ];
#pragma unroll
        for (int k = 0; k < TQ; ++k) {
            q01[k] = __shfl_up_sync(0xFFFFFFFFu, P01[k], 1, LPR);
            q23[k] = __shfl_up_sync(0xFFFFFFFFu, P23[k], 1, LPR);
            q4v[k] = __shfl_up_sync(0xFFFFFFFFu, P4[k], 1, LPR);
        }

        const int p = i - j;
        if ((unsigned)p < (unsigned)nquads) {
            u64 a01[TQ], a23[TQ];
            float a4[TQ];
#pragma unroll
            for (int k = 0; k < TQ; ++k) {
                a01[k] = (j == 0) ? 0ull : q01[k];
                a23[k] = (j == 0) ? 0ull : q23[k];
                a4[k]  = (j == 0) ? 0.0f : q4v[k];
            }

#pragma unroll
            for (int hh = 0; hh < HP; ++hh) {
                // W2 from shared: one 16B + one 4B load per hh per quad
                const ulonglong2 wp2 = *(const ulonglong2*)(w2p + hh * 8);
                const float w4 = w2p[hh * 8 + 4];
                float m = mem1[hh];
                const float c1 = cur1[hh];
                float r = (m > THR) ? 1.0f : 0.0f;   // reset from prev mem
#pragma unroll
                for (int k = 0; k < TQ; ++k) {
                    m = __fsub_rn(fmaf(BETA, m, c1), r);
                    const float s = (m > THR) ? 1.0f : 0.0f;
                    r = s;                            // spike(t) == reset(t+1)
                    u64 sd; DUP2(sd, s);
                    FMA2(a01[k], sd, wp2.x);
                    FMA2(a23[k], sd, wp2.y);
                    a4[k] = fmaf(s, w4, a4[k]);
                }
                mem1[hh] = m;
            }
#pragma unroll
            for (int k = 0; k < TQ; ++k) {
                P01[k] = a01[k]; P23[k] = a23[k]; P4[k] = a4[k];
            }

            if (storer) {
                const int t0 = TQ * p;
#pragma unroll
                for (int k = 0; k < TQ; ++k) {
                    const int t = t0 + k;
                    if (t < steps) {
                        float f0, f1, f2, f3;
                        UNPK2(f0, f1, P01[k]);
                        UNPK2(f2, f3, P23[k]);
                        const float f4 = P4[k];
                        const size_t ob = (size_t)t * bstr + (size_t)row * C_OUT;
                        float F[C_OUT] = {f0, f1, f2, f3, f4};
#pragma unroll
                        for (int c = 0; c < C_OUT; ++c) {
                            const float cur2 = __fadd_rn(F[c], rb2[c]); // dot + b2
                            float m2 = mem2[c];
                            const float r2 = (m2 > THR) ? 1.0f : 0.0f;
                            m2 = __fsub_rn(fmaf(BETA, m2, cur2), r2);
                            mem2[c] = m2;
                            out[ob + c]          = (m2 > THR) ? 1.0f : 0.0f;
                            out[memoff + ob + c] = m2;
                        }
                    }
                }
            }
        }
    }
}

extern "C" void kernel_launch(void* const* d_in, const int* in_sizes, int n_in,
                              void* d_out, int out_size)
{
    const float* x  = (const float*)d_in[0];
    const float* W1 = (const float*)d_in[1];
    const float* b1 = (const float*)d_in[2];
    const float* W2 = (const float*)d_in[3];
    const float* b2 = (const float*)d_in[4];
    float* out = (float*)d_out;

    const int B = in_sizes[0] / D_IN;
    const int steps = (int)((long long)out_size / (2LL * B * C_OUT));

    cudaFuncSetAttribute(snn_fused_kernel,
                         cudaFuncAttributeMaxDynamicSharedMemorySize, SMEM_BYTES);

    const int grid = (B + RPB - 1) / RPB;
    snn_fused_kernel<<<grid, TPB, SMEM_BYTES>>>(x, W1, b1, W2, b2, out, B, steps);
}